// round 1
// baseline (speedup 1.0000x reference)
#include <cuda_runtime.h>

// Problem constants
#define BB    64
#define HH    64
#define WWID  64
#define CIN   128
#define COUT  256
#define KHW   3
#define HO    62
#define WO    62
#define MM    (HO * WO)      // 3844 spatial outputs per sample
#define KTOT  (9 * CIN)      // 1152

// Tiling
#define BM    128
#define BN    64
#define BK    16
#define ASTRIDE 132          // padded k-major A stride (mult of 4 for LDS.128 alignment)
#define NTHREADS 256
#define NITER (9 * (CIN / BK))   // 72 k-iterations

__global__ __launch_bounds__(NTHREADS, 2)
void conv_aconnect_kernel(const float* __restrict__ X,
                          const float* __restrict__ W,
                          const float* __restrict__ bias,
                          const float* __restrict__ Werr,
                          const float* __restrict__ Berr,
                          float* __restrict__ out)
{
    __shared__ float As[2][BK * ASTRIDE];
    __shared__ float Bs[2][BK * BN];

    const int b  = blockIdx.z;
    const int n0 = blockIdx.x * BN;
    const int m0 = blockIdx.y * BM;

    const int tid  = threadIdx.x;
    const int ty   = tid >> 4;          // 0..15
    const int tx   = tid & 15;          // 0..15
    const int row0 = ty * 8;            // output row block within tile
    const int col0 = tx * 4;            // output col block within tile

    // ---- A (activation) load mapping: 512 float4 per tile, 2 per thread.
    // fidx -> m = fidx>>2 (spatial row in tile), kq = fidx&3 (which 4-ci group)
    int a_kq[2], a_m[2];
    const float* a_gp[2];
    bool a_valid[2];
    #pragma unroll
    for (int it = 0; it < 2; it++) {
        int fidx = tid + it * NTHREADS;
        int m  = fidx >> 2;
        int kq = fidx & 3;
        a_m[it]  = m;
        a_kq[it] = kq;
        int gm = m0 + m;
        a_valid[it] = (gm < MM);
        int ho = 0, wo = 0;
        if (a_valid[it]) { ho = gm / WO; wo = gm - ho * WO; }
        a_gp[it] = X + ((size_t)(b * HH + ho) * WWID + wo) * CIN + kq * 4;
    }

    // ---- B (weight) load mapping: 256 float4 per tile, 1 per thread.
    const int kb = tid >> 4;            // k row within BK
    const int nq = tid & 15;            // float4 col within BN
    const float* w_base  = W    + (size_t)kb * COUT + n0 + nq * 4;
    const float* we_base = Werr + (size_t)b * (9 * CIN * COUT)
                                + (size_t)kb * COUT + n0 + nq * 4;

    float acc[8][4];
    #pragma unroll
    for (int i = 0; i < 8; i++)
        #pragma unroll
        for (int j = 0; j < 4; j++) acc[i][j] = 0.0f;

    float4 ra[2], rw, re;

    // ---- Prologue: fill stage 0 (t=0: kh=kw=0, ci0=0)
    #pragma unroll
    for (int it = 0; it < 2; it++) {
        if (a_valid[it]) ra[it] = *(const float4*)(a_gp[it]);
        else             ra[it] = make_float4(0.f, 0.f, 0.f, 0.f);
    }
    rw = *(const float4*)(w_base);
    re = *(const float4*)(we_base);
    #pragma unroll
    for (int it = 0; it < 2; it++) {
        float* p = &As[0][a_kq[it] * 4 * ASTRIDE + a_m[it]];
        p[0]           = ra[it].x;
        p[ASTRIDE]     = ra[it].y;
        p[2 * ASTRIDE] = ra[it].z;
        p[3 * ASTRIDE] = ra[it].w;
    }
    {
        float4 bv = make_float4(rw.x * re.x, rw.y * re.y, rw.z * re.z, rw.w * re.w);
        *(float4*)&Bs[0][kb * BN + nq * 4] = bv;
    }
    __syncthreads();

    // ---- Main loop: double buffered, one __syncthreads per iteration
    for (int t = 0; t < NITER; t++) {
        const int cur = t & 1;
        const int tn  = t + 1;
        const bool has_next = (tn < NITER);

        if (has_next) {
            int khw = tn >> 3;                 // 0..8  (kh*3+kw)
            int cc  = tn & 7;                  // ci chunk
            int kh  = khw / 3;
            int kw  = khw - kh * 3;
            int ci0 = cc * BK;
            int aoff = (kh * WWID + kw) * CIN + ci0;
            #pragma unroll
            for (int it = 0; it < 2; it++) {
                if (a_valid[it]) ra[it] = *(const float4*)(a_gp[it] + aoff);
                else             ra[it] = make_float4(0.f, 0.f, 0.f, 0.f);
            }
            size_t woff = (size_t)(khw * CIN + ci0) * COUT;
            rw = *(const float4*)(w_base  + woff);
            re = *(const float4*)(we_base + woff);
        }

        const float* Ac = As[cur];
        const float* Bc = Bs[cur];
        #pragma unroll
        for (int k = 0; k < BK; k++) {
            float4 a0 = *(const float4*)&Ac[k * ASTRIDE + row0];
            float4 a1 = *(const float4*)&Ac[k * ASTRIDE + row0 + 4];
            float4 bf = *(const float4*)&Bc[k * BN + col0];
            float av[8] = {a0.x, a0.y, a0.z, a0.w, a1.x, a1.y, a1.z, a1.w};
            float bw[4] = {bf.x, bf.y, bf.z, bf.w};
            #pragma unroll
            for (int i = 0; i < 8; i++)
                #pragma unroll
                for (int j = 0; j < 4; j++)
                    acc[i][j] += av[i] * bw[j];
        }

        if (has_next) {
            const int nb = tn & 1;
            #pragma unroll
            for (int it = 0; it < 2; it++) {
                float* p = &As[nb][a_kq[it] * 4 * ASTRIDE + a_m[it]];
                p[0]           = ra[it].x;
                p[ASTRIDE]     = ra[it].y;
                p[2 * ASTRIDE] = ra[it].z;
                p[3 * ASTRIDE] = ra[it].w;
            }
            float4 bv = make_float4(rw.x * re.x, rw.y * re.y, rw.z * re.z, rw.w * re.w);
            *(float4*)&Bs[nb][kb * BN + nq * 4] = bv;
        }
        __syncthreads();
    }

    // ---- Epilogue: out = acc + bias*Berr
    const float4 bi = *(const float4*)&bias[n0 + col0];
    const float4 be = *(const float4*)&Berr[b * COUT + n0 + col0];
    const float4 bb = make_float4(bi.x * be.x, bi.y * be.y, bi.z * be.z, bi.w * be.w);

    #pragma unroll
    for (int i = 0; i < 8; i++) {
        int gm = m0 + row0 + i;
        if (gm < MM) {
            float4 v = make_float4(acc[i][0] + bb.x,
                                   acc[i][1] + bb.y,
                                   acc[i][2] + bb.z,
                                   acc[i][3] + bb.w);
            *(float4*)&out[((size_t)b * MM + gm) * COUT + n0 + col0] = v;
        }
    }
}

extern "C" void kernel_launch(void* const* d_in, const int* in_sizes, int n_in,
                              void* d_out, int out_size)
{
    const float* X    = (const float*)d_in[0];
    const float* W    = (const float*)d_in[1];
    const float* bias = (const float*)d_in[2];
    const float* Werr = (const float*)d_in[3];
    const float* Berr = (const float*)d_in[4];
    float* out = (float*)d_out;

    dim3 grid(COUT / BN, (MM + BM - 1) / BM, BB);   // (4, 31, 64)
    conv_aconnect_kernel<<<grid, NTHREADS>>>(X, W, bias, Werr, Berr, out);
}

// round 3
// speedup vs baseline: 2.1722x; 2.1722x over previous
#include <cuda_runtime.h>
#include <cstdint>

#define MM_    3844
#define CIN_   128
#define COUT_  256
#define KTOT_  1152
#define BM_    256
#define BN_    128
#define BK_    16
#define NTHR_  256
#define NT_    72          // k tiles: 9 khw * 8 ci-chunks
#define ASTR   20          // A smem stride in floats ([m][k] + pad)
#define BSTR   264         // B smem stride in floats ([k][n] + pad)

// dynamic smem layout (in floats)
#define OFF_A0  0
#define OFF_A1  (BM_ * ASTR)                     // 5120
#define OFF_B0  (2 * BM_ * ASTR)                 // 10240
#define OFF_B1  (2 * BM_ * ASTR + BK_ * BSTR)    // 14464
#define OFF_BBS (2 * BM_ * ASTR + 2 * BK_ * BSTR)// 18688
#define SMEM_BYTES ((OFF_BBS + BN_) * 4)         // 75264

__device__ __forceinline__ uint32_t to_tf32(float x) {
    uint32_t r;
    asm("cvt.rna.tf32.f32 %0, %1;" : "=r"(r) : "f"(x));
    return r;
}

__device__ __forceinline__ void mma_tf32(float c[4],
                                         uint32_t a0, uint32_t a1, uint32_t a2, uint32_t a3,
                                         uint32_t b0, uint32_t b1) {
    asm volatile(
        "mma.sync.aligned.m16n8k8.row.col.f32.tf32.tf32.f32 "
        "{%0,%1,%2,%3}, {%4,%5,%6,%7}, {%8,%9}, {%0,%1,%2,%3};"
        : "+f"(c[0]), "+f"(c[1]), "+f"(c[2]), "+f"(c[3])
        : "r"(a0), "r"(a1), "r"(a2), "r"(a3), "r"(b0), "r"(b1));
}

__global__ void __launch_bounds__(NTHR_, 1)
conv_mma_kernel(const float* __restrict__ X, const float* __restrict__ W,
                const float* __restrict__ bias, const float* __restrict__ Werr,
                const float* __restrict__ Berr, float* __restrict__ out)
{
    extern __shared__ float smf[];
    uint32_t* const Asm[2] = {(uint32_t*)(smf + OFF_A0), (uint32_t*)(smf + OFF_A1)};
    uint32_t* const Bsm[2] = {(uint32_t*)(smf + OFF_B0), (uint32_t*)(smf + OFF_B1)};
    float* const bbs = smf + OFF_BBS;

    const int tid  = threadIdx.x;
    const int lane = tid & 31;
    const int wid  = tid >> 5;
    const int wm   = wid >> 1;        // 0..3 (M dir)
    const int wn   = wid & 1;         // 0..1 (N dir)
    const int g    = lane >> 2;       // 0..7
    const int tq   = lane & 3;        // 0..3

    const int b  = blockIdx.z;
    const int m0 = blockIdx.y * BM_;
    const int n0 = blockIdx.x * BN_;

    if (tid < BN_) bbs[tid] = bias[n0 + tid] * Berr[b * COUT_ + n0 + tid];

    // ---- A fill mapping: 4 float4 per thread (m = tid>>2 + 64*it, kq = tid&3)
    const int mq = tid >> 2;
    const int kq = tid & 3;
    const float* Xrow[4];
    bool av[4];
    #pragma unroll
    for (int it = 0; it < 4; it++) {
        int mg = m0 + mq + it * 64;
        av[it] = (mg < MM_);
        int mc = av[it] ? mg : 0;
        int ho = mc / 62, wo = mc - ho * 62;
        Xrow[it] = X + (((size_t)b * 64 + ho) * 64 + wo) * CIN_ + kq * 4;
    }
    // ---- B fill mapping: 2 float4 per thread (k = tid>>5 + 8*it, n-quad = lane)
    const float* Wp = W + n0;
    const float* Ep = Werr + (size_t)b * ((size_t)KTOT_ * COUT_) + n0;

    float acc[4][8][4];
    #pragma unroll
    for (int i = 0; i < 4; i++)
        #pragma unroll
        for (int j = 0; j < 8; j++)
            #pragma unroll
            for (int q = 0; q < 4; q++) acc[i][j][q] = 0.0f;

    float4 ra[4], rw[2], re[2];

    auto load_regs = [&](int u) {
        const int khw = u >> 3, cc = u & 7;
        const int kh = khw / 3, kw = khw - 3 * kh;
        const int aoff = (kh * 64 + kw) * CIN_ + cc * BK_;
        #pragma unroll
        for (int it = 0; it < 4; it++)
            ra[it] = av[it] ? *(const float4*)(Xrow[it] + aoff)
                            : make_float4(0.f, 0.f, 0.f, 0.f);
        #pragma unroll
        for (int it = 0; it < 2; it++) {
            int bk = (tid >> 5) + it * 8;
            size_t goff = (size_t)(khw * CIN_ + cc * BK_ + bk) * COUT_ + lane * 4;
            rw[it] = *(const float4*)(Wp + goff);
            re[it] = *(const float4*)(Ep + goff);
        }
    };
    auto sts_regs = [&](int s) {
        uint32_t* An = Asm[s];
        uint32_t* Bn = Bsm[s];
        #pragma unroll
        for (int it = 0; it < 4; it++) {
            uint4 v = {to_tf32(ra[it].x), to_tf32(ra[it].y),
                       to_tf32(ra[it].z), to_tf32(ra[it].w)};
            *(uint4*)&An[(mq + it * 64) * ASTR + kq * 4] = v;
        }
        #pragma unroll
        for (int it = 0; it < 2; it++) {
            int bk = (tid >> 5) + it * 8;
            uint4 v = {to_tf32(rw[it].x * re[it].x), to_tf32(rw[it].y * re[it].y),
                       to_tf32(rw[it].z * re[it].z), to_tf32(rw[it].w * re[it].w)};
            *(uint4*)&Bn[bk * BSTR + lane * 4] = v;
        }
    };

    load_regs(0);
    sts_regs(0);
    __syncthreads();

    for (int t = 0; t < NT_; t++) {
        const int cur = t & 1;
        const bool hn = (t + 1 < NT_);
        if (hn) load_regs(t + 1);

        const uint32_t* Ab = Asm[cur];
        const uint32_t* Bb = Bsm[cur];
        #pragma unroll
        for (int k8 = 0; k8 < 2; k8++) {
            const int kb = k8 * 8;
            uint32_t af[4][4], bf[8][2];
            #pragma unroll
            for (int mt = 0; mt < 4; mt++) {
                int r = wm * 64 + mt * 16 + g;
                af[mt][0] = Ab[r * ASTR + kb + tq];
                af[mt][1] = Ab[(r + 8) * ASTR + kb + tq];
                af[mt][2] = Ab[r * ASTR + kb + 4 + tq];
                af[mt][3] = Ab[(r + 8) * ASTR + kb + 4 + tq];
            }
            #pragma unroll
            for (int nt = 0; nt < 8; nt++) {
                int c = wn * 64 + nt * 8 + g;
                bf[nt][0] = Bb[(kb + tq) * BSTR + c];
                bf[nt][1] = Bb[(kb + 4 + tq) * BSTR + c];
            }
            #pragma unroll
            for (int mt = 0; mt < 4; mt++)
                #pragma unroll
                for (int nt = 0; nt < 8; nt++)
                    mma_tf32(acc[mt][nt], af[mt][0], af[mt][1], af[mt][2], af[mt][3],
                             bf[nt][0], bf[nt][1]);
        }

        if (hn) sts_regs((t + 1) & 1);
        __syncthreads();
    }

    // ---- Epilogue: acc + bias*Berr -> out (float2 stores, 32B sectors per quad)
    #pragma unroll
    for (int mt = 0; mt < 4; mt++) {
        #pragma unroll
        for (int h = 0; h < 2; h++) {
            int rg = m0 + wm * 64 + mt * 16 + g + h * 8;
            if (rg < MM_) {
                float* op = out + ((size_t)b * MM_ + rg) * COUT_ + n0 + wn * 64 + tq * 2;
                #pragma unroll
                for (int nt = 0; nt < 8; nt++) {
                    float2 bb = *(const float2*)&bbs[wn * 64 + nt * 8 + tq * 2];
                    float2 v;
                    v.x = acc[mt][nt][2 * h + 0] + bb.x;
                    v.y = acc[mt][nt][2 * h + 1] + bb.y;
                    *(float2*)(op + nt * 8) = v;
                }
            }
        }
    }
}

extern "C" void kernel_launch(void* const* d_in, const int* in_sizes, int n_in,
                              void* d_out, int out_size)
{
    const float* X    = (const float*)d_in[0];
    const float* W    = (const float*)d_in[1];
    const float* bias = (const float*)d_in[2];
    const float* Werr = (const float*)d_in[3];
    const float* Berr = (const float*)d_in[4];
    float* out = (float*)d_out;

    cudaFuncSetAttribute(conv_mma_kernel,
                         cudaFuncAttributeMaxDynamicSharedMemorySize, SMEM_BYTES);
    dim3 grid(COUT_ / BN_, (MM_ + BM_ - 1) / BM_, 64);   // (2, 16, 64)
    conv_mma_kernel<<<grid, NTHR_, SMEM_BYTES>>>(X, W, bias, Werr, Berr, out);
}